// round 7
// baseline (speedup 1.0000x reference)
#include <cuda_runtime.h>
#include <cuda_bf16.h>

// Problem constants (fixed by the dataset)
#define B 8
#define L 2048
#define H 1024
#define C 64
#define NROWS (B * L)              // 16384
#define GRID  888                  // 148 SMs x 6 blocks -> exactly one wave

// Persistent scratch (zero-initialized at module load; self-reset each launch)
__device__ float        g_acc[B * C];
__device__ unsigned int g_count;

// ---------------------------------------------------------------------------
// Fused kernel, R7: exact one-wave launch (888 = 148x6 blocks), contiguous
// balanced row ranges (18-19 rows/block), fence-free atomic scatter with
// last-block finalize. Inner loop = R5's proven smem-weight version.
// ---------------------------------------------------------------------------
__global__ __launch_bounds__(256, 6) void fused_kernel(
    const float* __restrict__ feature,       // [B*L, H]
    const float* __restrict__ fc_weight,     // [H]
    const float* __restrict__ fc_bias,       // [1]
    const int*   __restrict__ position_list, // [B*C*2]
    float* __restrict__ out)                 // [B*C]
{
    __shared__ float sw[H];
    __shared__ float sproj[20];              // max 19 rows per block
    __shared__ bool  is_last;
    __shared__ int   s_sink;                 // forces atomic-return consumption

    const int tid  = threadIdx.x;
    const int blk  = blockIdx.x;
    const int warp = tid >> 5;
    const int lane = tid & 31;

    // Contiguous balanced row range for this block
    const int lo = (int)(((long long)blk       * NROWS) / GRID);
    const int hi = (int)(((long long)(blk + 1) * NROWS) / GRID);

    // Stage weights (4 KB) into smem
    #pragma unroll
    for (int i = tid; i < H; i += 256) sw[i] = fc_weight[i];
    __syncthreads();

    const float4* __restrict__ w4 = reinterpret_cast<const float4*>(sw);

    // --- Stage 1: warp-strided rows within [lo, hi) ---
    for (int r = lo + warp; r < hi; r += 8) {
        const float4* __restrict__ f4 =
            reinterpret_cast<const float4*>(feature + (size_t)r * H);
        float4 a4 = make_float4(0.f, 0.f, 0.f, 0.f);
        #pragma unroll
        for (int i = 0; i < 8; i++) {
            const int idx = i * 32 + lane;   // 0..255 float4s
            float4 v = f4[idx];
            float4 w = w4[idx];
            a4.x = fmaf(v.x, w.x, a4.x);
            a4.y = fmaf(v.y, w.y, a4.y);
            a4.z = fmaf(v.z, w.z, a4.z);
            a4.w = fmaf(v.w, w.w, a4.w);
        }
        float a = (a4.x + a4.y) + (a4.z + a4.w);
        #pragma unroll
        for (int o = 16; o > 0; o >>= 1)
            a += __shfl_xor_sync(0xFFFFFFFFu, a, o);
        if (lane == 0) sproj[r - lo] = a;
    }
    __syncthreads();

    // --- Stage 2: scatter; range may straddle one batch boundary ---
    const int sb0 = lo / L;
    const int sb1 = (hi - 1) / L;
    for (int sb = sb0; sb <= sb1; sb++) {
        // local (within-batch) window [wlo, whi)
        int wlo = lo - sb * L; if (wlo < 0) wlo = 0;
        int whi = hi - sb * L; if (whi > L) whi = L;
        if (tid < C) {
            const int si  = (sb * C + tid) * 2;
            const int src = position_list[si + 0];
            const int end = position_list[si + 1];
            int a = src > wlo ? src : wlo;
            int e = end < whi - 1 ? end : whi - 1;
            if (a <= e) {
                float s = 0.0f;
                const int base = sb * L - lo;        // sproj index offset
                for (int p = a; p <= e; p++)
                    s += sproj[p + base];
                // Value-returning atomic: L2 completion observed before the
                // (never-true) predicate -> release ordering for g_count
                // arrival without MEMBAR/CCTL.
                float old = atomicAdd(&g_acc[sb * C + tid], s);
                if (__float_as_uint(old) == 0xDEADBEEFu) s_sink = 1;
            }
        }
    }
    __syncthreads();   // all scatter atomics of this block have completed

    // --- Stage 3: arrive; last block finalizes ---
    if (tid == 0) {
        unsigned int prev = atomicAdd(&g_count, 1u);
        is_last = (prev == GRID - 1);
    }
    __syncthreads();

    if (is_last) {
        const float bias = fc_bias[0];
        #pragma unroll
        for (int k = 0; k < 2; k++) {
            const int i = tid + k * 256;     // 0..511
            const int src = position_list[i * 2 + 0];
            const int end = position_list[i * 2 + 1];
            const float v = __ldcg(&g_acc[i]);        // L2-coherent read
            out[i] = v / (float)(end - src + 1) + bias;
            __stcg(&g_acc[i], 0.0f);                  // reset for next launch
        }
        if (tid == 0) g_count = 0u;
    }
}

// ---------------------------------------------------------------------------
extern "C" void kernel_launch(void* const* d_in, const int* in_sizes, int n_in,
                              void* d_out, int out_size) {
    const float* feature       = (const float*)d_in[0];  // [B,L,H] f32
    const float* fc_weight     = (const float*)d_in[1];  // [1,H]   f32
    const float* fc_bias       = (const float*)d_in[2];  // [1]     f32
    const int*   position_list = (const int*)  d_in[3];  // [B,C,2] i32
    float* out = (float*)d_out;                          // [B*C,1] f32

    fused_kernel<<<GRID, 256>>>(feature, fc_weight, fc_bias,
                                position_list, out);
}

// round 8
// speedup vs baseline: 1.4475x; 1.4475x over previous
#include <cuda_runtime.h>
#include <cuda_bf16.h>

// Problem constants (fixed by the dataset)
#define B 8
#define L 2048
#define H 1024
#define C 64
#define NROWS   (B * L)            // 16384
#define NPASS   (NROWS / 8)        // 2048 passes, 8 rows each
#define GRID    592                // 148 SMs x 4 resident blocks, exact fill

// Persistent scratch (zero-initialized at module load; self-reset each launch)
__device__ float        g_acc[B * C];
__device__ unsigned int g_count;

// ---------------------------------------------------------------------------
// R8: persistent blocks, block-strided passes (1% per-SM imbalance vs 33% in
// R5), R5's proven statically-unrolled inner loop, smem-local span
// accumulation (zero global atomics in the stream), single flush at end.
// ---------------------------------------------------------------------------
__global__ __launch_bounds__(256, 4) void fused_kernel(
    const float* __restrict__ feature,       // [B*L, H]
    const float* __restrict__ fc_weight,     // [H]
    const float* __restrict__ fc_bias,       // [1]
    const int*   __restrict__ position_list, // [B*C*2]
    float* __restrict__ out)                 // [B*C]
{
    __shared__ float sw[H];                  // weights (4 KB)
    __shared__ float sacc[B * C];            // local span accumulator (2 KB)
    __shared__ float sproj[8];               // per-pass row projections
    __shared__ bool  is_last;
    __shared__ int   s_sink;                 // forces atomic-return consumption

    const int tid  = threadIdx.x;
    const int blk  = blockIdx.x;
    const int warp = tid >> 5;
    const int lane = tid & 31;

    // Stage weights; zero local accumulator
    #pragma unroll
    for (int i = tid; i < H; i += 256) sw[i] = fc_weight[i];
    #pragma unroll
    for (int k = 0; k < 2; k++) sacc[tid + k * 256] = 0.0f;
    __syncthreads();

    const float4* __restrict__ w4 = reinterpret_cast<const float4*>(sw);

    // --- Persistent pass loop: pass p covers rows [p*8, p*8+8) ---
    for (int p = blk; p < NPASS; p += GRID) {
        const int row0  = p * 8;             // global row of warp 0
        const int batch = row0 >> 11;        // row0 / L
        const int w0    = row0 & (L - 1);    // within-batch window start

        // Stage 1: warp-per-row projection (R5 inner loop)
        const float4* __restrict__ f4 = reinterpret_cast<const float4*>(
            feature + (size_t)(row0 + warp) * H);
        float4 a4 = make_float4(0.f, 0.f, 0.f, 0.f);
        #pragma unroll
        for (int i = 0; i < 8; i++) {
            const int idx = i * 32 + lane;   // 0..255 float4s
            float4 v = f4[idx];
            float4 w = w4[idx];
            a4.x = fmaf(v.x, w.x, a4.x);
            a4.y = fmaf(v.y, w.y, a4.y);
            a4.z = fmaf(v.z, w.z, a4.z);
            a4.w = fmaf(v.w, w.w, a4.w);
        }
        float a = (a4.x + a4.y) + (a4.z + a4.w);
        #pragma unroll
        for (int o = 16; o > 0; o >>= 1)
            a += __shfl_xor_sync(0xFFFFFFFFu, a, o);
        if (lane == 0) sproj[warp] = a;
        __syncthreads();

        // Stage 2: smem-local scatter (threads 0..63, conflict-free)
        if (tid < C) {
            const int si  = (batch * C + tid) * 2;   // L2-hot after pass 1
            const int src = position_list[si + 0];
            const int end = position_list[si + 1];
            int lo = src - w0; if (lo < 0) lo = 0;
            int hi = end - w0; if (hi > 7) hi = 7;
            if (lo <= hi) {
                float s = 0.0f;
                #pragma unroll
                for (int r = 0; r < 8; r++)
                    if (r >= lo && r <= hi) s += sproj[r];
                sacc[batch * C + tid] += s;
            }
        }
        __syncthreads();                     // sproj reuse + sacc visibility
    }

    // --- Flush local accumulator: <=2 value-returning atomics per thread ---
    #pragma unroll
    for (int k = 0; k < 2; k++) {
        const int i = tid + k * 256;         // 0..511
        const float s = sacc[i];
        if (s != 0.0f) {
            // Value-returning atomic: L2 completion observed before the
            // (never-true) predicate -> release ordering for g_count arrival
            // without MEMBAR/CCTL.
            float old = atomicAdd(&g_acc[i], s);
            if (__float_as_uint(old) == 0xDEADBEEFu) s_sink = 1;
        }
    }
    __syncthreads();                         // all flush atomics completed

    // --- Arrive; last block finalizes ---
    if (tid == 0) {
        unsigned int prev = atomicAdd(&g_count, 1u);
        is_last = (prev == GRID - 1);
    }
    __syncthreads();

    if (is_last) {
        const float bias = fc_bias[0];
        #pragma unroll
        for (int k = 0; k < 2; k++) {
            const int i = tid + k * 256;     // 0..511
            const int src = position_list[i * 2 + 0];
            const int end = position_list[i * 2 + 1];
            const float v = __ldcg(&g_acc[i]);        // L2-coherent read
            out[i] = v / (float)(end - src + 1) + bias;
            __stcg(&g_acc[i], 0.0f);                  // reset for next launch
        }
        if (tid == 0) g_count = 0u;
    }
}

// ---------------------------------------------------------------------------
extern "C" void kernel_launch(void* const* d_in, const int* in_sizes, int n_in,
                              void* d_out, int out_size) {
    const float* feature       = (const float*)d_in[0];  // [B,L,H] f32
    const float* fc_weight     = (const float*)d_in[1];  // [1,H]   f32
    const float* fc_bias       = (const float*)d_in[2];  // [1]     f32
    const int*   position_list = (const int*)  d_in[3];  // [B,C,2] i32
    float* out = (float*)d_out;                          // [B*C,1] f32

    fused_kernel<<<GRID, 256>>>(feature, fc_weight, fc_bias,
                                position_list, out);
}